// round 8
// baseline (speedup 1.0000x reference)
#include <cuda_runtime.h>

typedef unsigned long long u64;

// Packed folded weights: {Weff[2p][r3][co], Weff[2p+1][r3][co]} as f32x2
__device__ u64 g_wf2[8 * 27 * 32];
// Per-channel constant: bias*scale + beta - mean*scale
__device__ float g_cb[32];
// ci-pair-interleaved x: xi[b][d][h][pair][2w+par], par = ci&1
// (8 * 24 * 24 * 8 * 48 floats = 7.08 MB)
__device__ __align__(16) float g_xi[8 * 24 * 24 * 384];

// ---------------------------------------------------------------------------
// Pre-pass (fused): blocks 0..1727 interleave x into g_xi (one float4 per
// thread, read/write coalesced). Blocks 1728..1781 fold ConvTranspose taps +
// BN affine + pool 1/64 into packed weights.
// Tap sets per residue r (z = 2i - 1 + k, z-offset in [0,3]):
//   T(0) = {1,2}, T(1) = {0,1,2}, T(2) = {0}
// ---------------------------------------------------------------------------
__global__ void pre_kernel(const float* __restrict__ x,
                           const float* __restrict__ w,
                           const float* __restrict__ bias,
                           const float* __restrict__ gamma,
                           const float* __restrict__ beta,
                           const float* __restrict__ mean,
                           const float* __restrict__ var) {
    int bid = blockIdx.x;
    if (bid < 1728) {
        // 1728 * 256 = 442368 float4 = full g_xi
        int g = bid * 256 + threadIdx.x;
        int wq = g % 12;           // float4 within pair-row (2 w values)
        int t = g / 12;
        int pair = t & 7;  t >>= 3;
        int h = t % 24;    t /= 24;
        int d = t % 24;
        int b = t / 24;
        const float* r0 = x + ((((size_t)(b * 16 + 2 * pair)) * 24 + d) * 24 + h) * 24 + 2 * wq;
        float2 a = __ldg(reinterpret_cast<const float2*>(r0));
        float2 c = __ldg(reinterpret_cast<const float2*>(r0 + 13824));
        reinterpret_cast<float4*>(g_xi)[g] = make_float4(a.x, c.x, a.y, c.y);
        return;
    }

    int idx = (bid - 1728) * 256 + threadIdx.x;   // 0..13823
    if (idx >= 16 * 27 * 32) return;

    int co = idx & 31;
    int r3 = (idx >> 5) % 27;
    int ci = idx / (27 * 32);
    int rd = r3 / 9, rh = (r3 / 3) % 3, rw = r3 % 3;

    const int st[3] = {1, 0, 0};
    const int en[3] = {3, 3, 1};

    const float* wb = w + ((size_t)(ci * 32 + co)) * 27;
    float s = 0.f;
    for (int kd = st[rd]; kd < en[rd]; ++kd)
        for (int kh = st[rh]; kh < en[rh]; ++kh)
            for (int kw = st[rw]; kw < en[rw]; ++kw)
                s += wb[kd * 9 + kh * 3 + kw];

    float sc = gamma[co] * rsqrtf(var[co] + 1e-5f);
    float val = s * sc * (1.f / 64.f);
    ((float*)g_wf2)[((((ci >> 1) * 27) + r3) * 32 + co) * 2 + (ci & 1)] = val;

    if (idx < 32) {
        float sc2 = gamma[idx] * rsqrtf(var[idx] + 1e-5f);
        g_cb[idx] = bias[idx] * sc2 + beta[idx] - mean[idx] * sc2;
    }
}

__device__ __forceinline__ void fma2(u64& d, u64 a, u64 b) {
    asm("fma.rn.f32x2 %0, %1, %2, %0;" : "+l"(d) : "l"(a), "l"(b));
}
__device__ __forceinline__ void cp16(unsigned dst, const void* src) {
    asm volatile("cp.async.cg.shared.global [%0], [%1], 16;" :: "r"(dst), "l"(src));
}

// ---------------------------------------------------------------------------
// Main: 484 blocks x 256 threads; block handles tiles blockIdx and
// blockIdx+484 (tile = (b, od, oh)), double-buffered via cp.async.
//   buf[s] layout: [rd][rh][pair][48 floats] -> tile chunk per rd is
//   4608B contiguous in g_xi (h-major, pair-interleaved).
//   Warp wid computes ci pair wid; lane = co; fma.rn.f32x2 over 11 ow accs.
// ---------------------------------------------------------------------------
__global__ __launch_bounds__(256)
void conv_fused_kernel(float* __restrict__ out) {
    __shared__ __align__(16) char buf[2][13824];
    __shared__ float red[8][352];

    const int tid  = threadIdx.x;
    const int lane = tid & 31;   // co
    const int wid  = tid >> 5;   // ci pair

    // ---- stage both tiles (async) ----
#pragma unroll
    for (int s = 0; s < 2; ++s) {
        const int gw  = blockIdx.x + s * 484;
        const int b   = gw / 121;
        const int rem = gw - b * 121;
        const int od  = rem / 11;
        const int oh  = rem - od * 11;
        const float* base = g_xi + ((size_t)(b * 24 + 2 * od)) * 9216 + (size_t)(2 * oh) * 384;
        unsigned d0 = (unsigned)__cvta_generic_to_shared(buf[s]);
#pragma unroll
        for (int k = 0; k < 4; ++k) {
            int u = tid + k * 256;
            if (u < 864) {
                int rd = u / 288, r = u - rd * 288;
                cp16(d0 + u * 16, base + rd * 9216 + r * 4);
            }
        }
        asm volatile("cp.async.commit_group;");
    }

#pragma unroll
    for (int s = 0; s < 2; ++s) {
        if (s == 0) asm volatile("cp.async.wait_group 1;");
        else        asm volatile("cp.async.wait_group 0;");
        __syncthreads();

        const int gw  = blockIdx.x + s * 484;
        const int b   = gw / 121;
        const int rem = gw - b * 121;
        const int od  = rem / 11;
        const int oh  = rem - od * 11;

        u64 acc[11];
#pragma unroll
        for (int i = 0; i < 11; ++i) acc[i] = 0ull;

        const u64* wp = g_wf2 + (size_t)wid * 27 * 32 + lane;
        const char* xw = buf[s] + wid * 192;

#pragma unroll
        for (int rr = 0; rr < 9; ++rr) {
            u64 w0 = __ldg(wp + (rr * 3 + 0) * 32);
            u64 w1 = __ldg(wp + (rr * 3 + 1) * 32);
            u64 w2 = __ldg(wp + (rr * 3 + 2) * 32);
            const ulonglong2* rp = reinterpret_cast<const ulonglong2*>(xw + rr * 1536);

            u64 xv[14];
#pragma unroll
            for (int k = 0; k < 6; ++k) {
                ulonglong2 t = rp[k];
                xv[2 * k] = t.x; xv[2 * k + 1] = t.y;
            }
#pragma unroll
            for (int ow = 0; ow < 5; ++ow) {
                fma2(acc[ow], w0, xv[2 * ow]);
                fma2(acc[ow], w1, xv[2 * ow + 1]);
                fma2(acc[ow], w2, xv[2 * ow + 2]);
            }
            fma2(acc[5], w0, xv[10]);
            fma2(acc[5], w1, xv[11]);
#pragma unroll
            for (int k = 0; k < 6; ++k) {
                ulonglong2 t = rp[6 + k];
                xv[2 * k + 2] = t.x; xv[2 * k + 3] = t.y;
            }
            fma2(acc[5], w2, xv[2]);   // i = 12
#pragma unroll
            for (int ow = 6; ow < 11; ++ow) {
                fma2(acc[ow], w0, xv[2 * ow - 10]);
                fma2(acc[ow], w1, xv[2 * ow - 9]);
                fma2(acc[ow], w2, xv[2 * ow - 8]);
            }
        }

        // ---- cross-warp reduce + store ----
#pragma unroll
        for (int ow = 0; ow < 11; ++ow) {
            float lo, hi;
            asm("mov.b64 {%0, %1}, %2;" : "=f"(lo), "=f"(hi) : "l"(acc[ow]));
            red[wid][ow * 32 + lane] = lo + hi;
        }
        __syncthreads();

#pragma unroll
        for (int it = 0; it < 2; ++it) {
            int j = tid + it * 256;
            if (j < 352) {
                float ssum = g_cb[j & 31];
#pragma unroll
                for (int w = 0; w < 8; ++w) ssum += red[w][j];
                int ow = j >> 5, co = j & 31;
                out[((size_t)(b * 32 + co)) * 1331 + od * 121 + oh * 11 + ow] = ssum;
            }
        }
    }
}

extern "C" void kernel_launch(void* const* d_in, const int* in_sizes, int n_in,
                              void* d_out, int out_size) {
    const float* x     = (const float*)d_in[0];
    const float* w     = (const float*)d_in[1];
    const float* bias  = (const float*)d_in[2];
    const float* gamma = (const float*)d_in[3];
    const float* beta  = (const float*)d_in[4];
    const float* mean  = (const float*)d_in[5];
    const float* var   = (const float*)d_in[6];
    float* out = (float*)d_out;

    pre_kernel<<<1782, 256>>>(x, w, bias, gamma, beta, mean, var);
    conv_fused_kernel<<<484, 256>>>(out);
}